// round 10
// baseline (speedup 1.0000x reference)
#include <cuda_runtime.h>
#include <cstdint>

// Spatial GCN (24x24 grid, adj = D^-1 A + I => 5-point stencil) + weight
// + BatchNorm2d(train) + LeakyReLU(0.2), fully fused, single launch.
//
// R10: NO smem staging. Pass 1: direct-LDG stencil (ctr/up/dn quads from
// gmem, left/right via warp shuffle with lane-boundary fallbacks), y stored
// straight to d_out (which then sits in L2). Per-channel stats partials go
// through the proven gmem rendezvous (publish -> atomic arrive -> acquire
// spin -> fixed-order combine -> last reader resets for graph replay).
// Pass 2: re-read y from L2, normalize + LeakyReLU, overwrite in place.
// 288-thread CTAs, 4 per channel, no barriers in the stencil phase.

#define GRID_N  24
#define NN      576
#define NQ      144              // float4 quads per plane
#define BATCH   64
#define CSPLIT  4                // CTAs per channel
#define PLANES  (BATCH / CSPLIT) // 16 planes per CTA
#define PPC     4                // planes per chunk (2 per thread per chunk)
#define NCHUNK  (PLANES / PPC)   // 4
#define NTHR    288              // 2 plane-slots x 144 quads
#define BN_EPS  1e-4f
#define SLOPE   0.2f
#define MAXC    512

// rendezvous scratch (zero at load; self-reset to zero every launch)
__device__ float    g_part[MAXC * CSPLIT * 2];
__device__ unsigned g_cnt[MAXC];
__device__ unsigned g_done[MAXC];

__device__ __forceinline__ float invdeg(int i, int j) {
    const int d = 2 + (int)(i > 0 && i < GRID_N - 1) + (int)(j > 0 && j < GRID_N - 1);
    return (d == 2) ? 0.5f : ((d == 3) ? (1.f / 3.f) : 0.25f);
}

__global__ __launch_bounds__(NTHR, 4)
void gcn_bn_lrelu_kernel(const float* __restrict__ x,
                         const float* __restrict__ weight,
                         const float* __restrict__ gamma,
                         const float* __restrict__ beta,
                         float* __restrict__ out,
                         int C)
{
    __shared__ float red[24];
    __shared__ float s_sb[2];

    const int c    = blockIdx.x / CSPLIT;
    const int rank = blockIdx.x - c * CSPLIT;  // 0..3
    const int t    = threadIdx.x;              // 0..287
    const int lane = t & 31;
    const int ph   = t / NQ;                   // plane-slot 0..1
    const int q    = t - ph * NQ;              // quad 0..143
    const int row  = q / 6;
    const int col4 = q - row * 6;
    const int l0   = 4 * q;

    // ---- analytic coefficients folded with weight ----
    const float4 w4 = ((const float4*)(weight + (size_t)c * NN))[q];
    float cL[4], cR[4], cU[4], cD[4];
#pragma unroll
    for (int e = 0; e < 4; ++e) {
        const int j = 4 * col4 + e;
        const float we = (e == 0) ? w4.x : (e == 1) ? w4.y : (e == 2) ? w4.z : w4.w;
        cL[e] = (j > 0)           ? invdeg(row, j - 1) * we : 0.f;
        cR[e] = (j < GRID_N - 1)  ? invdeg(row, j + 1) * we : 0.f;
        cU[e] = (row > 0)         ? invdeg(row - 1, j) * we : 0.f;
        cD[e] = (row < GRID_N -1) ? invdeg(row + 1, j) * we : 0.f;
    }
    const int qU = (row > 0) ? q - 6 : q;
    const int qD = (row < GRID_N - 1) ? q + 6 : q;
    // lane-boundary fallbacks for the shuffled left/right neighbors
    const bool fbL = (lane == 0)  && (col4 > 0);
    const bool fbR = (lane == 31) && (col4 < 5);

    const float4* __restrict__ x4 = (const float4*)x;
    float4* __restrict__ out4 = (float4*)out;

#define STENCIL_Y(ctr, up, dn, lft, rgt, Y)                                   \
    {                                                                         \
        Y.x = w4.x*ctr.x; Y.x = fmaf(cL[0], lft,   Y.x); Y.x = fmaf(cR[0], ctr.y, Y.x); \
        Y.x = fmaf(cU[0], up.x, Y.x); Y.x = fmaf(cD[0], dn.x, Y.x);           \
        Y.y = w4.y*ctr.y; Y.y = fmaf(cL[1], ctr.x, Y.y); Y.y = fmaf(cR[1], ctr.z, Y.y); \
        Y.y = fmaf(cU[1], up.y, Y.y); Y.y = fmaf(cD[1], dn.y, Y.y);           \
        Y.z = w4.z*ctr.z; Y.z = fmaf(cL[2], ctr.y, Y.z); Y.z = fmaf(cR[2], ctr.w, Y.z); \
        Y.z = fmaf(cU[2], up.z, Y.z); Y.z = fmaf(cD[2], dn.z, Y.z);           \
        Y.w = w4.w*ctr.w; Y.w = fmaf(cL[3], ctr.z, Y.w); Y.w = fmaf(cR[3], rgt, Y.w);   \
        Y.w = fmaf(cU[3], up.w, Y.w); Y.w = fmaf(cD[3], dn.w, Y.w);           \
    }

    // ---- pass 1: stencil straight from gmem, y -> out, stats in regs ----
    float sum = 0.f, sq = 0.f;
#pragma unroll
    for (int ch = 0; ch < NCHUNK; ++ch) {
        const int lpA = ch * PPC + ph;          // two planes per thread
        const int lpB = lpA + 2;
        const int bA  = rank * PLANES + lpA;
        const int bB  = rank * PLANES + lpB;
        const float4* pA = x4 + (size_t)(bA * C + c) * NQ;
        const float4* pB = x4 + (size_t)(bB * C + c) * NQ;

        // batched independent loads (6 LDG.128)
        const float4 ctrA = pA[q], upA = pA[qU], dnA = pA[qD];
        const float4 ctrB = pB[q], upB = pB[qU], dnB = pB[qD];

        // left/right from neighboring lanes (plane edges have coeff 0;
        // cross-plane shfl garbage is multiplied by exactly 0)
        float lftA = __shfl_up_sync(0xffffffffu,  ctrA.w, 1);
        float rgtA = __shfl_down_sync(0xffffffffu, ctrA.x, 1);
        float lftB = __shfl_up_sync(0xffffffffu,  ctrB.w, 1);
        float rgtB = __shfl_down_sync(0xffffffffu, ctrB.x, 1);
        if (fbL) { lftA = ((const float*)pA)[l0 - 1]; lftB = ((const float*)pB)[l0 - 1]; }
        if (fbR) { rgtA = ((const float*)pA)[l0 + 4]; rgtB = ((const float*)pB)[l0 + 4]; }

        float4 yA, yB;
        STENCIL_Y(ctrA, upA, dnA, lftA, rgtA, yA);
        STENCIL_Y(ctrB, upB, dnB, lftB, rgtB, yB);

        sum += (yA.x + yA.y) + (yA.z + yA.w);
        sq = fmaf(yA.x, yA.x, sq); sq = fmaf(yA.y, yA.y, sq);
        sq = fmaf(yA.z, yA.z, sq); sq = fmaf(yA.w, yA.w, sq);
        sum += (yB.x + yB.y) + (yB.z + yB.w);
        sq = fmaf(yB.x, yB.x, sq); sq = fmaf(yB.y, yB.y, sq);
        sq = fmaf(yB.z, yB.z, sq); sq = fmaf(yB.w, yB.w, sq);

        out4[(size_t)(bA * C + c) * NQ + q] = yA;
        out4[(size_t)(bB * C + c) * NQ + q] = yB;
    }

    // ---- block reduction of this CTA's partial (sum, sq) ----
#pragma unroll
    for (int off = 16; off > 0; off >>= 1) {
        sum += __shfl_down_sync(0xffffffffu, sum, off);
        sq  += __shfl_down_sync(0xffffffffu, sq,  off);
    }
    const int warp = t >> 5;                   // 9 warps
    if (lane == 0) { red[warp] = sum; red[12 + warp] = sq; }
    __syncthreads();

    // ---- gmem rendezvous: publish partial, arrive, spin, combine ----
    if (t == 0) {
        float s = 0.f, qq = 0.f;
#pragma unroll
        for (int wi = 0; wi < NTHR / 32; ++wi) { s += red[wi]; qq += red[12 + wi]; }
        float* slot = g_part + ((size_t)c * CSPLIT + rank) * 2;
        slot[0] = s; slot[1] = qq;
        __threadfence();
        atomicAdd(&g_cnt[c], 1u);

        unsigned v;
        do {
            asm volatile("ld.acquire.gpu.u32 %0, [%1];"
                         : "=r"(v) : "l"(&g_cnt[c]) : "memory");
        } while (v < CSPLIT);

        float st = 0.f, qt = 0.f;
        const float* base = g_part + (size_t)c * CSPLIT * 2;
#pragma unroll
        for (int r = 0; r < CSPLIT; ++r) { st += base[2 * r]; qt += base[2 * r + 1]; }

        const float inv_n = 1.f / (float)(BATCH * NN);
        float mean = st * inv_n;
        float var  = fmaf(qt, inv_n, -mean * mean);
        float rstd = rsqrtf(var + BN_EPS);
        float sc   = gamma[c] * rstd;
        s_sb[0] = sc;
        s_sb[1] = fmaf(-mean, sc, beta[c]);

        __threadfence();
        unsigned d = atomicAdd(&g_done[c], 1u);
        if (d == CSPLIT - 1) {   // last reader resets for the next replay
            asm volatile("st.relaxed.gpu.u32 [%0], %1;" :: "l"(&g_done[c]), "r"(0u) : "memory");
            asm volatile("st.relaxed.gpu.u32 [%0], %1;" :: "l"(&g_cnt[c]),  "r"(0u) : "memory");
        }
    }
    __syncthreads();
    const float sc = s_sb[0], bi = s_sb[1];

    // ---- pass 2: y (L2-resident) -> normalize + LeakyReLU, in place ----
#pragma unroll
    for (int ch = 0; ch < NCHUNK; ++ch) {
        const int bA = rank * PLANES + ch * PPC + ph;
        const int bB = bA + 2;
        const size_t iA = (size_t)(bA * C + c) * NQ + q;
        const size_t iB = (size_t)(bB * C + c) * NQ + q;
        float4 vA = out4[iA];
        float4 vB = out4[iB];
        vA.x = fmaf(vA.x, sc, bi); vA.y = fmaf(vA.y, sc, bi);
        vA.z = fmaf(vA.z, sc, bi); vA.w = fmaf(vA.w, sc, bi);
        vB.x = fmaf(vB.x, sc, bi); vB.y = fmaf(vB.y, sc, bi);
        vB.z = fmaf(vB.z, sc, bi); vB.w = fmaf(vB.w, sc, bi);
        vA.x = (vA.x >= 0.f) ? vA.x : SLOPE * vA.x;
        vA.y = (vA.y >= 0.f) ? vA.y : SLOPE * vA.y;
        vA.z = (vA.z >= 0.f) ? vA.z : SLOPE * vA.z;
        vA.w = (vA.w >= 0.f) ? vA.w : SLOPE * vA.w;
        vB.x = (vB.x >= 0.f) ? vB.x : SLOPE * vB.x;
        vB.y = (vB.y >= 0.f) ? vB.y : SLOPE * vB.y;
        vB.z = (vB.z >= 0.f) ? vB.z : SLOPE * vB.z;
        vB.w = (vB.w >= 0.f) ? vB.w : SLOPE * vB.w;
        out4[iA] = vA;
        out4[iB] = vB;
    }
}

extern "C" void kernel_launch(void* const* d_in, const int* in_sizes, int n_in,
                              void* d_out, int out_size)
{
    const float* x      = (const float*)d_in[0];
    const float* weight = (const float*)d_in[2];
    const float* gamma  = (const float*)d_in[3];
    const float* beta   = (const float*)d_in[4];
    float* out = (float*)d_out;

    const int C = in_sizes[2] / NN;            // 512
    gcn_bn_lrelu_kernel<<<C * CSPLIT, NTHR>>>(x, weight, gamma, beta, out, C);
}

// round 11
// speedup vs baseline: 1.1769x; 1.1769x over previous
#include <cuda_runtime.h>
#include <cuda_pipeline_primitives.h>
#include <cstdint>

// Spatial GCN (24x24 grid, adj = D^-1 A + I => 5-point stencil) + weight
// + BatchNorm2d(train) + LeakyReLU(0.2), fully fused, single plain launch.
//
// R11: R8's compute core (576 threads, 32 planes in 4 chunks of 8, two
// planes per thread per chunk for ILP, pipelined y writeback, 2 CTAs/SM)
// WITHOUT clusters: the 2 per-channel partials meet through the proven gmem
// rendezvous (publish -> atomic arrive -> acquire spin -> fixed-order
// combine -> last reader resets counters for graph replay). Plain launch
// avoids the ~6us cluster-launch overhead measured in R7/R8.

#define GRID_N  24
#define NN      576
#define NQ      144              // float4 quads per plane
#define BATCH   64
#define CSPLIT  2                // CTAs per channel
#define PLANES  (BATCH / CSPLIT) // 32 planes per CTA
#define PPC     8                // planes per chunk
#define NCHUNK  (PLANES / PPC)   // 4
#define BN_EPS  1e-4f
#define SLOPE   0.2f
#define MAXC    512

// rendezvous scratch (zero at load; self-reset to zero every launch)
__device__ float    g_part[MAXC * CSPLIT * 2];
__device__ unsigned g_cnt[MAXC];
__device__ unsigned g_done[MAXC];

__device__ __forceinline__ float invdeg(int i, int j) {
    const int d = 2 + (int)(i > 0 && i < GRID_N - 1) + (int)(j > 0 && j < GRID_N - 1);
    return (d == 2) ? 0.5f : ((d == 3) ? (1.f / 3.f) : 0.25f);
}

__global__ __launch_bounds__(NN, 2)
void gcn_bn_lrelu_kernel(const float* __restrict__ x,
                         const float* __restrict__ weight,
                         const float* __restrict__ gamma,
                         const float* __restrict__ beta,
                         float* __restrict__ out,
                         int C)
{
    extern __shared__ float buf[];             // PLANES * NN floats (73728 B)
    __shared__ float red[64];
    __shared__ float s_sb[2];

    const int c    = blockIdx.x / CSPLIT;
    const int rank = blockIdx.x - c * CSPLIT;  // 0..1
    const int t    = threadIdx.x;              // 0..575
    const int lane = t & 31;
    const int pq   = t / NQ;                   // 0..3
    const int q    = t - pq * NQ;              // quad 0..143
    const int row  = q / 6;
    const int col4 = q - row * 6;
    const int l0   = 4 * q;

    // ---- prologue: 4 cp.async groups, 2 planes per thread per group ----
    const float4* __restrict__ x4 = (const float4*)x;
    float4* buf4 = (float4*)buf;
#pragma unroll
    for (int s = 0; s < NCHUNK; ++s) {
#pragma unroll
        for (int h = 0; h < 2; ++h) {
            const int lp = s * PPC + pq + h * 4;           // local plane
            const int b  = rank * PLANES + lp;             // global plane
            __pipeline_memcpy_async(&buf4[(size_t)lp * NQ + q],
                                    x4 + ((size_t)(b * C + c)) * NQ + q, 16);
        }
        __pipeline_commit();
    }

    // ---- analytic coefficients folded with weight ----
    const float4 w4 = ((const float4*)(weight + (size_t)c * NN))[q];
    float cL[4], cR[4], cU[4], cD[4];
#pragma unroll
    for (int e = 0; e < 4; ++e) {
        const int j = 4 * col4 + e;
        const float we = (e == 0) ? w4.x : (e == 1) ? w4.y : (e == 2) ? w4.z : w4.w;
        cL[e] = (j > 0)           ? invdeg(row, j - 1) * we : 0.f;
        cR[e] = (j < GRID_N - 1)  ? invdeg(row, j + 1) * we : 0.f;
        cU[e] = (row > 0)         ? invdeg(row - 1, j) * we : 0.f;
        cD[e] = (row < GRID_N -1) ? invdeg(row + 1, j) * we : 0.f;
    }

    const int oL = (col4 > 0) ? l0 - 1 : l0;
    const int oR = (col4 < 5) ? l0 + 4 : l0;
    const int qU = (row > 0) ? q - 6 : q;
    const int qD = (row < GRID_N - 1) ? q + 6 : q;

#define DO_STENCIL(LP, Y)                                                     \
    {                                                                         \
        const float*  xb  = buf + (size_t)(LP) * NN;                          \
        const float4* xb4 = (const float4*)xb;                                \
        const float4 ctr = xb4[q];                                            \
        const float4 up  = xb4[qU];                                           \
        const float4 dn  = xb4[qD];                                           \
        const float  lft = xb[oL];                                            \
        const float  rgt = xb[oR];                                            \
        Y.x = w4.x*ctr.x; Y.x = fmaf(cL[0], lft,   Y.x); Y.x = fmaf(cR[0], ctr.y, Y.x); \
        Y.x = fmaf(cU[0], up.x, Y.x); Y.x = fmaf(cD[0], dn.x, Y.x);           \
        Y.y = w4.y*ctr.y; Y.y = fmaf(cL[1], ctr.x, Y.y); Y.y = fmaf(cR[1], ctr.z, Y.y); \
        Y.y = fmaf(cU[1], up.y, Y.y); Y.y = fmaf(cD[1], dn.y, Y.y);           \
        Y.z = w4.z*ctr.z; Y.z = fmaf(cL[2], ctr.y, Y.z); Y.z = fmaf(cR[2], ctr.w, Y.z); \
        Y.z = fmaf(cU[2], up.z, Y.z); Y.z = fmaf(cD[2], dn.z, Y.z);           \
        Y.w = w4.w*ctr.w; Y.w = fmaf(cL[3], ctr.z, Y.w); Y.w = fmaf(cR[3], rgt, Y.w);   \
        Y.w = fmaf(cU[3], up.w, Y.w); Y.w = fmaf(cD[3], dn.w, Y.w);           \
    }

#define ACC(Y)                                                                \
    {                                                                         \
        sum += (Y.x + Y.y) + (Y.z + Y.w);                                     \
        sq = fmaf(Y.x, Y.x, sq); sq = fmaf(Y.y, Y.y, sq);                     \
        sq = fmaf(Y.z, Y.z, sq); sq = fmaf(Y.w, Y.w, sq);                     \
    }

    // ---- stats pass: 4 chunks, writeback pipelined into the next window ----
    float sum = 0.f, sq = 0.f;
    float4 yA, yB;

    __pipeline_wait_prior(NCHUNK - 1);
    __syncthreads();
    DO_STENCIL(pq,     yA); ACC(yA);
    DO_STENCIL(pq + 4, yB); ACC(yB);

#pragma unroll
    for (int ch = 1; ch < NCHUNK; ++ch) {
        __pipeline_wait_prior(NCHUNK - 1 - ch);
        __syncthreads();   // reads of chunk ch-1 done AND chunk ch data ready
        buf4[(size_t)((ch - 1) * PPC + pq)     * NQ + q] = yA;
        buf4[(size_t)((ch - 1) * PPC + pq + 4) * NQ + q] = yB;
        DO_STENCIL(ch * PPC + pq,     yA); ACC(yA);
        DO_STENCIL(ch * PPC + pq + 4, yB); ACC(yB);
    }
    __syncthreads();       // reads of last chunk done
    buf4[(size_t)((NCHUNK - 1) * PPC + pq)     * NQ + q] = yA;
    buf4[(size_t)((NCHUNK - 1) * PPC + pq + 4) * NQ + q] = yB;

    // ---- block reduction of this CTA's partial (sum, sq) ----
#pragma unroll
    for (int off = 16; off > 0; off >>= 1) {
        sum += __shfl_down_sync(0xffffffffu, sum, off);
        sq  += __shfl_down_sync(0xffffffffu, sq,  off);
    }
    const int warp = t >> 5;                   // 18 warps
    if (lane == 0) { red[warp] = sum; red[32 + warp] = sq; }
    __syncthreads();

    // ---- gmem rendezvous across the channel's 2 CTAs ----
    if (t == 0) {
        float s = 0.f, qq = 0.f;
#pragma unroll
        for (int wi = 0; wi < NN / 32; ++wi) { s += red[wi]; qq += red[32 + wi]; }
        float* slot = g_part + ((size_t)c * CSPLIT + rank) * 2;
        slot[0] = s; slot[1] = qq;
        __threadfence();
        atomicAdd(&g_cnt[c], 1u);

        unsigned v;
        do {
            asm volatile("ld.acquire.gpu.u32 %0, [%1];"
                         : "=r"(v) : "l"(&g_cnt[c]) : "memory");
        } while (v < CSPLIT);

        float st = 0.f, qt = 0.f;
        const float* base = g_part + (size_t)c * CSPLIT * 2;
#pragma unroll
        for (int r = 0; r < CSPLIT; ++r) { st += base[2 * r]; qt += base[2 * r + 1]; }

        const float inv_n = 1.f / (float)(BATCH * NN);
        float mean = st * inv_n;
        float var  = fmaf(qt, inv_n, -mean * mean);
        float rstd = rsqrtf(var + BN_EPS);
        float sc   = gamma[c] * rstd;
        s_sb[0] = sc;
        s_sb[1] = fmaf(-mean, sc, beta[c]);

        __threadfence();
        unsigned d = atomicAdd(&g_done[c], 1u);
        if (d == CSPLIT - 1) {   // last reader resets for the next replay
            asm volatile("st.relaxed.gpu.u32 [%0], %1;" :: "l"(&g_done[c]), "r"(0u) : "memory");
            asm volatile("st.relaxed.gpu.u32 [%0], %1;" :: "l"(&g_cnt[c]),  "r"(0u) : "memory");
        }
    }
    __syncthreads();
    const float sc = s_sb[0], bi = s_sb[1];

    // ---- apply pass: own y quads -> normalize + LeakyReLU + STG.128 ----
    float4* __restrict__ out4 = (float4*)out;
#pragma unroll
    for (int ch = 0; ch < NCHUNK; ++ch) {
#pragma unroll
        for (int h = 0; h < 2; ++h) {
            const int lp = ch * PPC + pq + h * 4;
            const int b  = rank * PLANES + lp;
            float4 v = buf4[(size_t)lp * NQ + q];
            v.x = fmaf(v.x, sc, bi); v.y = fmaf(v.y, sc, bi);
            v.z = fmaf(v.z, sc, bi); v.w = fmaf(v.w, sc, bi);
            v.x = (v.x >= 0.f) ? v.x : SLOPE * v.x;
            v.y = (v.y >= 0.f) ? v.y : SLOPE * v.y;
            v.z = (v.z >= 0.f) ? v.z : SLOPE * v.z;
            v.w = (v.w >= 0.f) ? v.w : SLOPE * v.w;
            out4[(size_t)(b * C + c) * NQ + q] = v;
        }
    }
}

extern "C" void kernel_launch(void* const* d_in, const int* in_sizes, int n_in,
                              void* d_out, int out_size)
{
    const float* x      = (const float*)d_in[0];
    const float* weight = (const float*)d_in[2];
    const float* gamma  = (const float*)d_in[3];
    const float* beta   = (const float*)d_in[4];
    float* out = (float*)d_out;

    const int C = in_sizes[2] / NN;            // 512
    const size_t smem = (size_t)PLANES * NN * sizeof(float);   // 73728 B

    cudaFuncSetAttribute(gcn_bn_lrelu_kernel,
                         cudaFuncAttributeMaxDynamicSharedMemorySize, (int)smem);
    gcn_bn_lrelu_kernel<<<C * CSPLIT, NN, smem>>>(x, weight, gamma, beta, out, C);
}